// round 2
// baseline (speedup 1.0000x reference)
#include <cuda_runtime.h>
#include <stdint.h>

// StationSelectionAggregator:
//   schedule: [B, WIN, N_ST]  one-hot float32
//   csi:      [B, N_ST, N_SUB, WIN] float32
//   out:      [B, WIN, N_SUB] float32
//   out[b,w,s] = csi[b, t(b,w), s, w]  (exact selection, schedule is one-hot).
//
// DRAM traffic is floored at ~(512+64) MB because every 128B csi line is
// ~98.6% likely to contain a selected element. So read csi DENSELY with
// float4-coalesced streaming loads (best DRAM request stream) and select
// in registers, instead of gathering partial sectors.
#define B_    32
#define NST   8
#define NSUB  256
#define WIN   2048

__global__ __launch_bounds__(256)
void station_select_dense_kernel(const float* __restrict__ sched,
                                 const float* __restrict__ csi,
                                 float* __restrict__ out) {
    // blockIdx.x : w tile (WIN/32 = 64), .y : s tile (NSUB/32 = 8), .z : batch
    __shared__ float tile[32][33];   // [s_local][w_local], padded
    __shared__ int   tw[32];         // selected station per w in this tile

    const int b   = blockIdx.z;
    const int w0  = blockIdx.x * 32;
    const int s0  = blockIdx.y * 32;
    const int tid = threadIdx.x;     // 0..255

    // --- recover station index per w from the one-hot row (exact 0.0/1.0) ---
    if (tid < 32) {
        const float4* sp = reinterpret_cast<const float4*>(
            sched + ((size_t)b * WIN + (size_t)(w0 + tid)) * NST);
        float4 a = sp[0];
        float4 c = sp[1];
        float tf = a.y + 2.f * a.z + 3.f * a.w +
                   4.f * c.x + 5.f * c.y + 6.f * c.z + 7.f * c.w;
        tw[tid] = (int)(tf + 0.5f);
    }
    __syncthreads();

    // --- dense coalesced read of ALL 8 planes, select in registers ---
    // thread layout: w4 = tid&7 (float4 index along w), sl = tid>>3 (s row)
    const int w4 = tid & 7;          // covers w_local 4*w4 .. 4*w4+3
    const int sl = tid >> 3;         // 0..31
    const int wl = 4 * w4;

    const int t0 = tw[wl + 0];
    const int t1 = tw[wl + 1];
    const int t2 = tw[wl + 2];
    const int t3 = tw[wl + 3];

    const size_t plane_stride4 = (size_t)NSUB * WIN / 4;   // float4 elems per plane
    const float4* p = reinterpret_cast<const float4*>(csi)
                    + ((size_t)b * NST * NSUB + (size_t)(s0 + sl)) * (WIN / 4)
                    + (size_t)(w0 / 4 + w4);

    // batch all 8 independent 16B loads first (max MLP), streaming hint
    float4 v[NST];
#pragma unroll
    for (int t = 0; t < NST; t++)
        v[t] = __ldcs(p + (size_t)t * plane_stride4);

    float a0 = 0.f, a1 = 0.f, a2 = 0.f, a3 = 0.f;
#pragma unroll
    for (int t = 0; t < NST; t++) {
        if (t == t0) a0 = v[t].x;
        if (t == t1) a1 = v[t].y;
        if (t == t2) a2 = v[t].z;
        if (t == t3) a3 = v[t].w;
    }

    // conflict-free scalar stores: bank = (sl + 4*w4 + i) & 31, all distinct per i
    tile[sl][wl + 0] = a0;
    tile[sl][wl + 1] = a1;
    tile[sl][wl + 2] = a2;
    tile[sl][wl + 3] = a3;
    __syncthreads();

    // --- transposed coalesced writes along s ---
    const int tx = tid & 31;         // s index within tile
    const int ty = tid >> 5;         // 0..7
#pragma unroll
    for (int r = 0; r < 4; r++) {
        const int wr = ty + r * 8;   // w_local
        out[((size_t)b * WIN + (size_t)(w0 + wr)) * NSUB + (size_t)(s0 + tx)]
            = tile[tx][wr];
    }
}

extern "C" void kernel_launch(void* const* d_in, const int* in_sizes, int n_in,
                              void* d_out, int out_size) {
    const float* sched = (const float*)d_in[0];
    const float* csi   = (const float*)d_in[1];
    if (n_in >= 2 && in_sizes[0] != 524288) {   // schedule = 32*2048*8
        sched = (const float*)d_in[1];
        csi   = (const float*)d_in[0];
    }
    float* out = (float*)d_out;

    dim3 block(256, 1, 1);
    dim3 grid(WIN / 32, NSUB / 32, B_);
    station_select_dense_kernel<<<grid, block>>>(sched, csi, out);
}

// round 3
// speedup vs baseline: 1.0147x; 1.0147x over previous
#include <cuda_runtime.h>
#include <stdint.h>

// StationSelectionAggregator:
//   schedule: [B, WIN, N_ST]  one-hot float32
//   csi:      [B, N_ST, N_SUB, WIN] float32
//   out:      [B, WIN, N_SUB] float32
//   out[b,w,s] = csi[b, t(b,w), s, w]  (exact selection; schedule is one-hot).
//
// DRAM traffic is floored at ~578 MB (every 128B csi line is ~98.6% likely to
// be touched; each line feeds exactly one block -> no reuse). Optimize purely
// for achieved bandwidth: gather reads coalesced along w, 8 batched loads per
// thread per phase (high MLP), streaming cache hints, smem transpose for
// coalesced writes along s.
#define B_    32
#define NST   8
#define NSUB  256
#define WIN   2048
#define STILE 64   // s rows per block

__global__ __launch_bounds__(256)
void station_select_kernel(const float* __restrict__ sched,
                           const float* __restrict__ csi,
                           float* __restrict__ out) {
    // blockIdx.x : w tile (WIN/32 = 64)  [fastest -> contiguous lines across CTAs]
    // blockIdx.y : s tile (NSUB/STILE = 4)
    // blockIdx.z : batch  (32)
    __shared__ float tile[STILE][33];   // [s_local][w_local], +1 pad
    __shared__ int   tw[32];            // selected station per w in this tile

    const int b   = blockIdx.z;
    const int w0  = blockIdx.x * 32;
    const int s0  = blockIdx.y * STILE;
    const int tid = threadIdx.x;        // 0..255
    const int tx  = tid & 31;           // w_local / s_local depending on phase
    const int ty  = tid >> 5;           // 0..7

    // --- recover station index per w (exact: one-hot values are 0.0/1.0) ---
    if (tid < 32) {
        const float4* sp = reinterpret_cast<const float4*>(
            sched + ((size_t)b * WIN + (size_t)(w0 + tid)) * NST);
        float4 a = sp[0];
        float4 c = sp[1];
        float tf = a.y + 2.f * a.z + 3.f * a.w +
                   4.f * c.x + 5.f * c.y + 6.f * c.z + 7.f * c.w;
        tw[tid] = (int)(tf + 0.5f);
    }
    __syncthreads();

    // --- gather reads: coalesced along w (tx), 8 independent loads batched ---
    const int t = tw[tx];
    const float* p = csi + (((size_t)(b * NST + t) * NSUB + (size_t)s0) * WIN)
                         + (size_t)(w0 + tx);

    float v[8];
#pragma unroll
    for (int r = 0; r < 8; r++) {
        const int sl = ty + r * 8;                       // 0..63
        v[r] = __ldcs(p + (size_t)sl * WIN);
    }
#pragma unroll
    for (int r = 0; r < 8; r++) {
        const int sl = ty + r * 8;
        tile[sl][tx] = v[r];                             // bank (sl+tx)&31: conflict-free
    }
    __syncthreads();

    // --- transposed writes: coalesced along s (tx), 8 stores per thread ---
#pragma unroll
    for (int r = 0; r < 4; r++) {
        const int wl = ty + r * 8;                       // w_local 0..31
        float* orow = out + ((size_t)b * WIN + (size_t)(w0 + wl)) * NSUB + (size_t)s0;
#pragma unroll
        for (int h = 0; h < 2; h++) {
            const int sl = tx + 32 * h;                  // 0..63
            __stcs(orow + sl, tile[sl][wl]);             // bank (sl+wl)&31: conflict-free
        }
    }
}

extern "C" void kernel_launch(void* const* d_in, const int* in_sizes, int n_in,
                              void* d_out, int out_size) {
    const float* sched = (const float*)d_in[0];
    const float* csi   = (const float*)d_in[1];
    if (n_in >= 2 && in_sizes[0] != 524288) {   // schedule = 32*2048*8 elems
        sched = (const float*)d_in[1];
        csi   = (const float*)d_in[0];
    }
    float* out = (float*)d_out;

    dim3 block(256, 1, 1);
    dim3 grid(WIN / 32, NSUB / STILE, B_);
    station_select_kernel<<<grid, block>>>(sched, csi, out);
}